// round 10
// baseline (speedup 1.0000x reference)
#include <cuda_runtime.h>
#include <cstdint>

#define BATCH   2048
#define TT      50
#define NNODES  23
#define FF      4
#define HH      64
#define FUT     10
#define BPC     4                 // batches per CTA
#define ROWS    (BPC*NNODES)      // 92
#define MPAD    96
#define THREADS 512
#define CS      132               // sC row stride (floats): 64 spa | 64 h | 4 pad
#define WS      192               // sWt row stride (floats)
#define SS      68                // sSup row stride

// smem floats
#define SMEM_FLOATS (24576 + MPAD*CS + MPAD*SS + BPC*NNODES*24 + ROWS*FF + 256 + 64 + 128 + 64 + 64 + 2048 + 32 + 128 + 4)

typedef unsigned long long u64;

__device__ __forceinline__ void fma2(u64& d, u64 a, u64 b) {
    asm("fma.rn.f32x2 %0, %1, %2, %0;" : "+l"(d) : "l"(a), "l"(b));
}
__device__ __forceinline__ float2 unpk(u64 v) {
    float2 r; asm("mov.b64 {%0, %1}, %2;" : "=f"(r.x), "=f"(r.y) : "l"(v)); return r;
}
__device__ __forceinline__ u64 dup2(float a) {
    u64 r; asm("mov.b64 %0, {%1, %1};" : "=l"(r) : "f"(a)); return r;
}
__device__ __forceinline__ float sigmoidf_(float x) {
    return __fdividef(1.f, 1.f + __expf(-x));
}
__device__ __forceinline__ float tanhf_(float x) {
    return __fdividef(2.f, 1.f + __expf(-2.f * x)) - 1.f;
}

// one K-half (64 k) of the gate GEMM: 6 rows x (2j x 3 gates)
// A column = kb*4 (kb0=0 -> spa cols 0..63 ; kb0=16 -> h cols 64..127)
// B row    = kb*4+kk (0..63 -> W_ih^T ; 64..127 -> W_hh^T)
__device__ __forceinline__ void gemm_half(const float* __restrict__ sC,
                                          const float* __restrict__ sWt,
                                          const int rofs[6], int jr,
                                          int kb0,
                                          u64 acc[6][3]) {
#pragma unroll 2
    for (int kb = kb0; kb < kb0 + 16; ++kb) {
        float4 a[6];
#pragma unroll
        for (int q = 0; q < 6; ++q)
            a[q] = *(const float4*)(sC + rofs[q] + kb*4);
#pragma unroll
        for (int kk = 0; kk < 4; ++kk) {
            const float* wr = sWt + (kb*4 + kk)*WS + jr;
            u64 br = *(const u64*)(wr);
            u64 bz = *(const u64*)(wr + 64);
            u64 bn = *(const u64*)(wr + 128);
#pragma unroll
            for (int q = 0; q < 6; ++q) {
                float f = kk==0 ? a[q].x : kk==1 ? a[q].y : kk==2 ? a[q].z : a[q].w;
                u64 d = dup2(f);
                fma2(acc[q][0], d, br);
                fma2(acc[q][1], d, bz);
                fma2(acc[q][2], d, bn);
            }
        }
    }
}

extern "C" __global__ void __launch_bounds__(THREADS, 1)
gwm_kernel(const float* __restrict__ x_seq, const float* __restrict__ adj_seq,
           const float* __restrict__ W_gcn, const float* __restrict__ b_gcn,
           const float* __restrict__ W_ih,  const float* __restrict__ W_hh,
           const float* __restrict__ b_ih,  const float* __restrict__ b_hh,
           const float* __restrict__ W_d1,  const float* __restrict__ b_d1,
           const float* __restrict__ W_d2,  const float* __restrict__ b_d2,
           float* __restrict__ out)
{
    extern __shared__ float sm[];
    float* sWt  = sm;                 // [k=0..127][j=0..191]  k<64: W_ih^T, k>=64: W_hh^T
    float* sC   = sWt  + 24576;       // [96][132] : cols 0..63 spa, 64..127 h
    float* sSup = sC   + MPAD*CS;     // [96][68]
    float* sAdj = sSup + MPAD*SS;     // [r][24]
    float* sX   = sAdj + BPC*NNODES*24;
    float* sWg  = sX   + ROWS*FF;     // [j][4]
    float* sbg  = sWg  + 256;
    float* sbrz = sbg  + 64;          // b_ih+b_hh for j 0..127 (r,z)
    float* sbin = sbrz + 128;         // b_ih[128+j]
    float* sbhn = sbin + 64;          // b_hh[128+j]
    float* sWd1 = sbhn + 64;          // [q][64]
    float* sbd1 = sWd1 + 2048;
    float* sWd2 = sbd1 + 32;          // [f][32]
    float* sbd2 = sWd2 + 128;

    const int tid  = threadIdx.x;
    const int w    = tid >> 5;
    const int lane = tid & 31;
    const int b0   = blockIdx.x * BPC;

    // GEMM tile mapping: 16 warps; warp covers 8 m-slots (ml) in half wm, 4 j-pairs (ng)
    const int wm = w >> 3;            // 0..1  -> M half (rows wm*48 .. wm*48+47)
    const int wn = w & 7;             // 0..7
    const int ml = lane & 7;          // 0..7
    const int ng = lane >> 3;         // 0..3
    const int jr = (wn*4 + ng)*2;     // even j 0..62
    // 6 rows per thread, stride-8 interleaved for conflict-free A loads
    int rofs[6];
#pragma unroll
    for (int q = 0; q < 6; ++q) rofs[q] = (wm*48 + q*8 + ml)*CS;

    // ---- one-time setup ----
    for (int e = tid; e < 192*64; e += THREADS) {
        int j = e >> 6, k = e & 63;
        sWt[k*WS + j]        = W_ih[j*64 + k];
        sWt[(64+k)*WS + j]   = W_hh[j*64 + k];
    }
    for (int e = tid; e < 256;  e += THREADS) sWg[e]  = W_gcn[e];
    for (int e = tid; e < 2048; e += THREADS) sWd1[e] = W_d1[e];
    if (tid < 64)  sbg[tid]  = b_gcn[tid];
    if (tid < 128) sbrz[tid] = b_ih[tid] + b_hh[tid];
    if (tid >= 128 && tid < 192) sbin[tid-128] = b_ih[tid];
    if (tid >= 192 && tid < 256) sbhn[tid-192] = b_hh[tid-64];   // b_hh[128..191]
    if (tid < 32)  sbd1[tid] = b_d1[tid];
    if (tid < 128) sWd2[tid] = W_d2[tid];
    if (tid < 4)   sbd2[tid] = b_d2[tid];
    for (int e = tid; e < MPAD*CS; e += THREADS) sC[e] = 0.f;   // spa=0, h0=0
    __syncthreads();

    for (int t = 0; t < TT + FUT; ++t) {
        const bool hist = (t < TT);
        if (hist) {
            for (int e = tid; e < BPC*NNODES*NNODES; e += THREADS) {
                int bl = e / (NNODES*NNODES);
                int i  = e - bl*(NNODES*NNODES);
                int n  = i / NNODES, m = i - n*NNODES;
                sAdj[(bl*NNODES + n)*24 + m] =
                    adj_seq[((size_t)(b0+bl)*TT + t)*(NNODES*NNODES) + i];
            }
            for (int e = tid; e < ROWS*FF; e += THREADS) {
                int bl = e / (NNODES*FF);
                int i  = e - bl*(NNODES*FF);
                sX[e] = x_seq[((size_t)(b0+bl)*TT + t)*(NNODES*FF) + i];
            }
            __syncthreads();
        }

        // ---- phase 1: support = x @ Wg^T + bg ----
        for (int e = tid; e < ROWS*HH; e += THREADS) {
            int r = e >> 6, j = e & 63;
            const float* xp = sX + r*FF;
            float v = sbg[j];
            v = fmaf(xp[0], sWg[j*4+0], v);
            v = fmaf(xp[1], sWg[j*4+1], v);
            v = fmaf(xp[2], sWg[j*4+2], v);
            v = fmaf(xp[3], sWg[j*4+3], v);
            sSup[r*SS + j] = v;
        }
        __syncthreads();

        // ---- phase 2: spa = relu(adj @ support) -> sC[:, 0..63] ----
        {
            const int rh = lane >> 4, jq = lane & 15;
            for (int p = w; p < 46; p += 16) {
                int r  = 2*p + rh;                   // 0..91
                int bl = r / NNODES;
                const float* arow = sAdj + r*24;
                const float* supb = sSup + (bl*NNODES)*SS;
                u64 a0 = 0ull, a1 = 0ull;
#pragma unroll
                for (int m = 0; m < NNODES; ++m) {
                    u64 am = dup2(arow[m]);
                    ulonglong2 s = *(const ulonglong2*)(supb + m*SS + 4*jq);
                    fma2(a0, am, s.x);
                    fma2(a1, am, s.y);
                }
                float2 f0 = unpk(a0), f1 = unpk(a1);
                float4 o;
                o.x = fmaxf(f0.x, 0.f); o.y = fmaxf(f0.y, 0.f);
                o.z = fmaxf(f1.x, 0.f); o.w = fmaxf(f1.y, 0.f);
                *(float4*)(sC + r*CS + 4*jq) = o;
            }
        }
        __syncthreads();

        // ---- phase 3: gate GEMM (all 512 threads) ----
        u64 accLo[6][3], accHi[6][3];
#pragma unroll
        for (int q = 0; q < 6; ++q)
#pragma unroll
            for (int g = 0; g < 3; ++g) { accLo[q][g] = 0ull; accHi[q][g] = 0ull; }

        gemm_half(sC, sWt, rofs, jr, 0,  accLo);   // spa (cols 0..63)  @ W_ih^T
        gemm_half(sC, sWt, rofs, jr, 16, accHi);   // h   (cols 64..127)@ W_hh^T

        // ---- GRU epilogue (in registers) ----
        float hnew[6][2];
        {
            const float2 brz_r = *(const float2*)(sbrz + jr);
            const float2 brz_z = *(const float2*)(sbrz + 64 + jr);
            const float2 bin_n = *(const float2*)(sbin + jr);
            const float2 bhn_n = *(const float2*)(sbhn + jr);
#pragma unroll
            for (int q = 0; q < 6; ++q) {
                float2 rL = unpk(accLo[q][0]), rH = unpk(accHi[q][0]);
                float2 zL = unpk(accLo[q][1]), zH = unpk(accHi[q][1]);
                float2 nI = unpk(accLo[q][2]), nH = unpk(accHi[q][2]);
                float r0 = sigmoidf_(rL.x + rH.x + brz_r.x);
                float r1 = sigmoidf_(rL.y + rH.y + brz_r.y);
                float z0 = sigmoidf_(zL.x + zH.x + brz_z.x);
                float z1 = sigmoidf_(zL.y + zH.y + brz_z.y);
                float n0 = tanhf_(nI.x + bin_n.x + r0*(nH.x + bhn_n.x));
                float n1 = tanhf_(nI.y + bin_n.y + r1*(nH.y + bhn_n.y));
                float2 ho = *(const float2*)(sC + rofs[q] + 64 + jr);
                hnew[q][0] = (1.f - z0)*n0 + z0*ho.x;
                hnew[q][1] = (1.f - z1)*n1 + z1*ho.y;
            }
        }
        __syncthreads();    // all GEMM reads of sC done
#pragma unroll
        for (int q = 0; q < 6; ++q)
            *(float2*)(sC + rofs[q] + 64 + jr) = make_float2(hnew[q][0], hnew[q][1]);
        __syncthreads();

        // ---- decode (future steps only) ----
        if (!hist) {
            const int s = t - TT;
            if (w < 8) {
                const int q0 = w * 4;
#pragma unroll
                for (int rg = 0; rg < 3; ++rg) {
                    int r  = rg*32 + lane;
                    int rr = (r < ROWS) ? r : 0;
                    const float* hp = sC + rr*CS + 64;
                    float acc[4] = {0.f,0.f,0.f,0.f};
#pragma unroll 4
                    for (int kq = 0; kq < 16; ++kq) {
                        float4 hh = *(const float4*)(hp + kq*4);
#pragma unroll
                        for (int jj = 0; jj < 4; ++jj) {
                            const float4 wd = *(const float4*)(sWd1 + (q0+jj)*64 + kq*4);
                            float a = acc[jj];
                            a = fmaf(hh.x, wd.x, a); a = fmaf(hh.y, wd.y, a);
                            a = fmaf(hh.z, wd.z, a); a = fmaf(hh.w, wd.w, a);
                            acc[jj] = a;
                        }
                    }
                    if (r < ROWS) {
#pragma unroll
                        for (int jj = 0; jj < 4; ++jj)
                            sSup[r*SS + q0 + jj] = fmaxf(acc[jj] + sbd1[q0+jj], 0.f);
                    }
                }
            }
            __syncthreads();
            for (int e = tid; e < ROWS*FF; e += THREADS) {
                int r = e >> 2, f = e & 3;
                float v = sbd2[f];
#pragma unroll
                for (int q = 0; q < 32; ++q)
                    v = fmaf(sSup[r*SS + q], sWd2[f*32 + q], v);
                sX[e] = v;
                int bl = r / NNODES, n = r - bl*NNODES;
                out[(((size_t)(b0+bl)*FUT + s)*NNODES + n)*FF + f] = v;
            }
            __syncthreads();
        }
    }
}

extern "C" void kernel_launch(void* const* d_in, const int* in_sizes, int n_in,
                              void* d_out, int out_size) {
    const float* x_seq  = (const float*)d_in[0];
    const float* adj    = (const float*)d_in[1];
    const float* W_gcn  = (const float*)d_in[2];
    const float* b_gcn  = (const float*)d_in[3];
    const float* W_ih   = (const float*)d_in[4];
    const float* W_hh   = (const float*)d_in[5];
    const float* b_ih   = (const float*)d_in[6];
    const float* b_hh   = (const float*)d_in[7];
    const float* W_d1   = (const float*)d_in[8];
    const float* b_d1   = (const float*)d_in[9];
    const float* W_d2   = (const float*)d_in[10];
    const float* b_d2   = (const float*)d_in[11];
    float* out = (float*)d_out;

    const int smem_bytes = SMEM_FLOATS * (int)sizeof(float);
    cudaFuncSetAttribute(gwm_kernel, cudaFuncAttributeMaxDynamicSharedMemorySize, smem_bytes);
    gwm_kernel<<<BATCH / BPC, THREADS, smem_bytes>>>(
        x_seq, adj, W_gcn, b_gcn, W_ih, W_hh, b_ih, b_hh,
        W_d1, b_d1, W_d2, b_d2, out);
}

// round 11
// speedup vs baseline: 1.5665x; 1.5665x over previous
#include <cuda_runtime.h>
#include <cstdint>

#define BATCH   2048
#define TT      50
#define NNODES  23
#define FF      4
#define HH      64
#define FUT     10
#define BPC     4                 // batches per CTA
#define ROWS    (BPC*NNODES)      // 92
#define MPAD    96
#define THREADS 1024
#define CS      132               // sC row stride (floats): 64 spa | 64 h | 4 pad
#define WS      192               // sWt row stride (floats)
#define SS      68                // sSup row stride

// smem floats
#define SMEM_FLOATS (24576 + MPAD*CS + MPAD*SS + ROWS*24 + ROWS*FF + 256 + 64 + 128 + 64 + 64 + 2048 + 32 + 128 + 4)

typedef unsigned long long u64;

__device__ __forceinline__ void fma2(u64& d, u64 a, u64 b) {
    asm("fma.rn.f32x2 %0, %1, %2, %0;" : "+l"(d) : "l"(a), "l"(b));
}
__device__ __forceinline__ float2 unpk(u64 v) {
    float2 r; asm("mov.b64 {%0, %1}, %2;" : "=f"(r.x), "=f"(r.y) : "l"(v)); return r;
}
__device__ __forceinline__ u64 dup2(float a) {
    u64 r; asm("mov.b64 %0, {%1, %1};" : "=l"(r) : "f"(a)); return r;
}
__device__ __forceinline__ float sigmoidf_(float x) {
    return __fdividef(1.f, 1.f + __expf(-x));
}
__device__ __forceinline__ float tanhf_(float x) {
    return __fdividef(2.f, 1.f + __expf(-2.f * x)) - 1.f;
}

// one K-half (64 k): A col = kb*4 (kb0=0 -> spa ; kb0=16 -> h),
// B row = kb*4+kk (0..63 W_ih^T ; 64..127 W_hh^T).
// aR/aZ accumulate across both halves; aN is per-half.
__device__ __forceinline__ void gemm_half(const float* __restrict__ sC,
                                          const float* __restrict__ sWt,
                                          const int rofs[3], int jr, int kb0,
                                          u64 aR[3], u64 aZ[3], u64 aN[3]) {
#pragma unroll 2
    for (int kb = kb0; kb < kb0 + 16; ++kb) {
        float4 a0 = *(const float4*)(sC + rofs[0] + kb*4);
        float4 a1 = *(const float4*)(sC + rofs[1] + kb*4);
        float4 a2 = *(const float4*)(sC + rofs[2] + kb*4);
#pragma unroll
        for (int kk = 0; kk < 4; ++kk) {
            const float* wr = sWt + (kb*4 + kk)*WS + jr;
            u64 br = *(const u64*)(wr);
            u64 bz = *(const u64*)(wr + 64);
            u64 bn = *(const u64*)(wr + 128);
            float f0 = kk==0 ? a0.x : kk==1 ? a0.y : kk==2 ? a0.z : a0.w;
            float f1 = kk==0 ? a1.x : kk==1 ? a1.y : kk==2 ? a1.z : a1.w;
            float f2 = kk==0 ? a2.x : kk==1 ? a2.y : kk==2 ? a2.z : a2.w;
            u64 d0 = dup2(f0), d1 = dup2(f1), d2 = dup2(f2);
            fma2(aR[0], d0, br); fma2(aZ[0], d0, bz); fma2(aN[0], d0, bn);
            fma2(aR[1], d1, br); fma2(aZ[1], d1, bz); fma2(aN[1], d1, bn);
            fma2(aR[2], d2, br); fma2(aZ[2], d2, bz); fma2(aN[2], d2, bn);
        }
    }
}

extern "C" __global__ void __launch_bounds__(THREADS, 1)
gwm_kernel(const float* __restrict__ x_seq, const float* __restrict__ adj_seq,
           const float* __restrict__ W_gcn, const float* __restrict__ b_gcn,
           const float* __restrict__ W_ih,  const float* __restrict__ W_hh,
           const float* __restrict__ b_ih,  const float* __restrict__ b_hh,
           const float* __restrict__ W_d1,  const float* __restrict__ b_d1,
           const float* __restrict__ W_d2,  const float* __restrict__ b_d2,
           float* __restrict__ out)
{
    extern __shared__ float sm[];
    float* sWt  = sm;                 // [k=0..127][j=0..191]  k<64: W_ih^T, k>=64: W_hh^T
    float* sC   = sWt  + 24576;       // [96][132] : cols 0..63 spa, 64..127 h
    float* sSup = sC   + MPAD*CS;     // [96][68]
    float* sAdj = sSup + MPAD*SS;     // [r][24]
    float* sX   = sAdj + ROWS*24;
    float* sWg  = sX   + ROWS*FF;     // [j][4]
    float* sbg  = sWg  + 256;
    float* sbrz = sbg  + 64;          // b_ih+b_hh for j 0..127 (r,z)
    float* sbin = sbrz + 128;         // b_ih[128+j]
    float* sbhn = sbin + 64;          // b_hh[128+j]
    float* sWd1 = sbhn + 64;          // [q][64]
    float* sbd1 = sWd1 + 2048;
    float* sWd2 = sbd1 + 32;          // [f][32]
    float* sbd2 = sWd2 + 128;

    const int tid  = threadIdx.x;
    const int w    = tid >> 5;
    const int lane = tid & 31;
    const int b0   = blockIdx.x * BPC;

    // GEMM tile mapping: 32 warps = 4 m-groups (24 rows each) x 8 j-groups
    const int wm = w >> 3;            // 0..3
    const int wn = w & 7;             // 0..7
    const int ml = lane & 7;          // 0..7
    const int ng = lane >> 3;         // 0..3
    const int jr = (wn*4 + ng)*2;     // even j 0..62
    int rofs[3];
#pragma unroll
    for (int q = 0; q < 3; ++q) rofs[q] = (wm*24 + ml*3 + q)*CS;

    // ---- one-time setup ----
    for (int e = tid; e < 192*64; e += THREADS) {
        int j = e >> 6, k = e & 63;
        sWt[k*WS + j]        = W_ih[j*64 + k];
        sWt[(64+k)*WS + j]   = W_hh[j*64 + k];
    }
    for (int e = tid; e < 256;  e += THREADS) sWg[e]  = W_gcn[e];
    for (int e = tid; e < 2048; e += THREADS) sWd1[e] = W_d1[e];
    if (tid < 64)  sbg[tid]  = b_gcn[tid];
    if (tid < 128) sbrz[tid] = b_ih[tid] + b_hh[tid];
    if (tid >= 128 && tid < 192) sbin[tid-128] = b_ih[tid];
    if (tid >= 192 && tid < 256) sbhn[tid-192] = b_hh[tid-64];   // b_hh[128..191]
    if (tid < 32)  sbd1[tid] = b_d1[tid];
    if (tid < 128) sWd2[tid] = W_d2[tid];
    if (tid < 4)   sbd2[tid] = b_d2[tid];
    for (int e = tid; e < MPAD*CS; e += THREADS) sC[e] = 0.f;   // spa=0, h0=0
    __syncthreads();

    for (int t = 0; t < TT + FUT; ++t) {
        const bool hist = (t < TT);
        if (hist) {
            for (int e = tid; e < ROWS*NNODES; e += THREADS) {
                int bl = e / (NNODES*NNODES);
                int i  = e - bl*(NNODES*NNODES);
                int n  = i / NNODES, m = i - n*NNODES;
                sAdj[(bl*NNODES + n)*24 + m] =
                    adj_seq[((size_t)(b0+bl)*TT + t)*(NNODES*NNODES) + i];
            }
            for (int e = tid; e < ROWS*FF; e += THREADS) {
                int bl = e / (NNODES*FF);
                int i  = e - bl*(NNODES*FF);
                sX[e] = x_seq[((size_t)(b0+bl)*TT + t)*(NNODES*FF) + i];
            }
            __syncthreads();
        }

        // ---- phase 1: support = x @ Wg^T + bg ----
        for (int e = tid; e < ROWS*HH; e += THREADS) {
            int r = e >> 6, j = e & 63;
            const float* xp = sX + r*FF;
            float v = sbg[j];
            v = fmaf(xp[0], sWg[j*4+0], v);
            v = fmaf(xp[1], sWg[j*4+1], v);
            v = fmaf(xp[2], sWg[j*4+2], v);
            v = fmaf(xp[3], sWg[j*4+3], v);
            sSup[r*SS + j] = v;
        }
        __syncthreads();

        // ---- phase 2: spa = relu(adj @ support) -> sC[:, 0..63] ----
        {
            const int rh = lane >> 4, jq = lane & 15;
            for (int p = w; p < 46; p += 32) {
                int r  = 2*p + rh;                   // 0..91
                int bl = r / NNODES;
                const float* arow = sAdj + r*24;
                const float* supb = sSup + (bl*NNODES)*SS;
                u64 a0 = 0ull, a1 = 0ull;
#pragma unroll
                for (int m = 0; m < NNODES; ++m) {
                    u64 am = dup2(arow[m]);
                    ulonglong2 s = *(const ulonglong2*)(supb + m*SS + 4*jq);
                    fma2(a0, am, s.x);
                    fma2(a1, am, s.y);
                }
                float2 f0 = unpk(a0), f1 = unpk(a1);
                float4 o;
                o.x = fmaxf(f0.x, 0.f); o.y = fmaxf(f0.y, 0.f);
                o.z = fmaxf(f1.x, 0.f); o.w = fmaxf(f1.y, 0.f);
                *(float4*)(sC + r*CS + 4*jq) = o;
            }
        }
        __syncthreads();

        // ---- phase 3: gate GEMM (all 1024 threads) ----
        u64 aR[3], aZ[3], aNlo[3], aNhi[3];
#pragma unroll
        for (int q = 0; q < 3; ++q) { aR[q]=0ull; aZ[q]=0ull; aNlo[q]=0ull; aNhi[q]=0ull; }

        gemm_half(sC, sWt, rofs, jr, 0,  aR, aZ, aNlo);  // spa @ W_ih^T
        gemm_half(sC, sWt, rofs, jr, 16, aR, aZ, aNhi);  // h   @ W_hh^T

        // ---- GRU epilogue (in registers) ----
        float hnew[3][2];
        {
            const float2 brz_r = *(const float2*)(sbrz + jr);
            const float2 brz_z = *(const float2*)(sbrz + 64 + jr);
            const float2 bin_n = *(const float2*)(sbin + jr);
            const float2 bhn_n = *(const float2*)(sbhn + jr);
#pragma unroll
            for (int q = 0; q < 3; ++q) {
                float2 rv = unpk(aR[q]);
                float2 zv = unpk(aZ[q]);
                float2 nI = unpk(aNlo[q]);
                float2 nH = unpk(aNhi[q]);
                float r0 = sigmoidf_(rv.x + brz_r.x);
                float r1 = sigmoidf_(rv.y + brz_r.y);
                float z0 = sigmoidf_(zv.x + brz_z.x);
                float z1 = sigmoidf_(zv.y + brz_z.y);
                float n0 = tanhf_(nI.x + bin_n.x + r0*(nH.x + bhn_n.x));
                float n1 = tanhf_(nI.y + bin_n.y + r1*(nH.y + bhn_n.y));
                float2 ho = *(const float2*)(sC + rofs[q] + 64 + jr);
                hnew[q][0] = (1.f - z0)*n0 + z0*ho.x;
                hnew[q][1] = (1.f - z1)*n1 + z1*ho.y;
            }
        }
        __syncthreads();    // all GEMM reads of sC done
#pragma unroll
        for (int q = 0; q < 3; ++q)
            *(float2*)(sC + rofs[q] + 64 + jr) = make_float2(hnew[q][0], hnew[q][1]);
        __syncthreads();

        // ---- decode (future steps only) ----
        if (!hist) {
            const int s = t - TT;
            if (w < 8) {
                const int q0 = w * 4;
#pragma unroll
                for (int rg = 0; rg < 3; ++rg) {
                    int r  = rg*32 + lane;
                    int rr = (r < ROWS) ? r : 0;
                    const float* hp = sC + rr*CS + 64;
                    float acc[4] = {0.f,0.f,0.f,0.f};
#pragma unroll 4
                    for (int kq = 0; kq < 16; ++kq) {
                        float4 hh = *(const float4*)(hp + kq*4);
#pragma unroll
                        for (int jj = 0; jj < 4; ++jj) {
                            const float4 wd = *(const float4*)(sWd1 + (q0+jj)*64 + kq*4);
                            float a = acc[jj];
                            a = fmaf(hh.x, wd.x, a); a = fmaf(hh.y, wd.y, a);
                            a = fmaf(hh.z, wd.z, a); a = fmaf(hh.w, wd.w, a);
                            acc[jj] = a;
                        }
                    }
                    if (r < ROWS) {
#pragma unroll
                        for (int jj = 0; jj < 4; ++jj)
                            sSup[r*SS + q0 + jj] = fmaxf(acc[jj] + sbd1[q0+jj], 0.f);
                    }
                }
            }
            __syncthreads();
            for (int e = tid; e < ROWS*FF; e += THREADS) {
                int r = e >> 2, f = e & 3;
                float v = sbd2[f];
#pragma unroll
                for (int q = 0; q < 32; ++q)
                    v = fmaf(sSup[r*SS + q], sWd2[f*32 + q], v);
                sX[e] = v;
                int bl = r / NNODES, n = r - bl*NNODES;
                out[(((size_t)(b0+bl)*FUT + s)*NNODES + n)*FF + f] = v;
            }
            __syncthreads();
        }
    }
}

extern "C" void kernel_launch(void* const* d_in, const int* in_sizes, int n_in,
                              void* d_out, int out_size) {
    const float* x_seq  = (const float*)d_in[0];
    const float* adj    = (const float*)d_in[1];
    const float* W_gcn  = (const float*)d_in[2];
    const float* b_gcn  = (const float*)d_in[3];
    const float* W_ih   = (const float*)d_in[4];
    const float* W_hh   = (const float*)d_in[5];
    const float* b_ih   = (const float*)d_in[6];
    const float* b_hh   = (const float*)d_in[7];
    const float* W_d1   = (const float*)d_in[8];
    const float* b_d1   = (const float*)d_in[9];
    const float* W_d2   = (const float*)d_in[10];
    const float* b_d2   = (const float*)d_in[11];
    float* out = (float*)d_out;

    const int smem_bytes = SMEM_FLOATS * (int)sizeof(float);
    cudaFuncSetAttribute(gwm_kernel, cudaFuncAttributeMaxDynamicSharedMemorySize, smem_bytes);
    gwm_kernel<<<BATCH / BPC, THREADS, smem_bytes>>>(
        x_seq, adj, W_gcn, b_gcn, W_ih, W_hh, b_ih, b_hh,
        W_d1, b_d1, W_d2, b_d2, out);
}

// round 12
// speedup vs baseline: 1.6551x; 1.0566x over previous
#include <cuda_runtime.h>
#include <cstdint>

#define BATCH   2048
#define TT      50
#define NNODES  23
#define FF      4
#define HH      64
#define FUT     10
#define BPC     2                 // batches per CTA
#define ROWS    (BPC*NNODES)      // 46
#define MPAD    48
#define THREADS 512
#define CS      132               // sC row stride (floats): 64 spa | 64 h | 4 pad
#define SS      68                // sSup row stride

// packed weights: [k2][g][p][4] = {w[2k2][2p], w[2k2][2p+1], w[2k2+1][2p], w[2k2+1][2p+1]}
#define SZ_WP   (64*3*32*4)       // 24576
#define SMEM_FLOATS (SZ_WP + MPAD*CS + MPAD*SS + ROWS*24 + ROWS*FF + 256 + 64 + 128 + 64 + 64 + 2048 + 32 + 128 + 4)

typedef unsigned long long u64;

__device__ __forceinline__ void fma2(u64& d, u64 a, u64 b) {
    asm("fma.rn.f32x2 %0, %1, %2, %0;" : "+l"(d) : "l"(a), "l"(b));
}
__device__ __forceinline__ float2 unpk(u64 v) {
    float2 r; asm("mov.b64 {%0, %1}, %2;" : "=f"(r.x), "=f"(r.y) : "l"(v)); return r;
}
__device__ __forceinline__ u64 dup2(float a) {
    u64 r; asm("mov.b64 %0, {%1, %1};" : "=l"(r) : "f"(a)); return r;
}
__device__ __forceinline__ float sigmoidf_(float x) {
    return __fdividef(1.f, 1.f + __expf(-x));
}
__device__ __forceinline__ float tanhf_(float x) {
    return __fdividef(2.f, 1.f + __expf(-2.f * x)) - 1.f;
}

// one K-half (64 k): A col = kb*4 (kb0=0 -> spa ; kb0=16 -> h).
// Weight k row = kb*4.. (k<64 -> W_ih^T ; k>=64 -> W_hh^T), via packed sWp.
// aR/aZ accumulate across both halves; aN per-half.
__device__ __forceinline__ void gemm_half(const float* __restrict__ sC,
                                          const float* __restrict__ sWp,
                                          const int rofs[3], int p4, int kb0,
                                          u64 aR[3], u64 aZ[3], u64 aN[3]) {
#pragma unroll 2
    for (int kb = kb0; kb < kb0 + 16; ++kb) {
        float4 a0 = *(const float4*)(sC + rofs[0] + kb*4);
        float4 a1 = *(const float4*)(sC + rofs[1] + kb*4);
        float4 a2 = *(const float4*)(sC + rofs[2] + kb*4);
#pragma unroll
        for (int k2h = 0; k2h < 2; ++k2h) {
            const int k2 = 2*kb + k2h;
            const float* bp = sWp + k2*384 + p4;
            ulonglong2 br2 = *(const ulonglong2*)(bp);
            ulonglong2 bz2 = *(const ulonglong2*)(bp + 128);
            ulonglong2 bn2 = *(const ulonglong2*)(bp + 256);
            float e0 = k2h ? a0.z : a0.x, o0 = k2h ? a0.w : a0.y;
            float e1 = k2h ? a1.z : a1.x, o1 = k2h ? a1.w : a1.y;
            float e2 = k2h ? a2.z : a2.x, o2 = k2h ? a2.w : a2.y;
            u64 de0 = dup2(e0), do0 = dup2(o0);
            u64 de1 = dup2(e1), do1 = dup2(o1);
            u64 de2 = dup2(e2), do2 = dup2(o2);
            fma2(aR[0], de0, br2.x); fma2(aR[0], do0, br2.y);
            fma2(aZ[0], de0, bz2.x); fma2(aZ[0], do0, bz2.y);
            fma2(aN[0], de0, bn2.x); fma2(aN[0], do0, bn2.y);
            fma2(aR[1], de1, br2.x); fma2(aR[1], do1, br2.y);
            fma2(aZ[1], de1, bz2.x); fma2(aZ[1], do1, bz2.y);
            fma2(aN[1], de1, bn2.x); fma2(aN[1], do1, bn2.y);
            fma2(aR[2], de2, br2.x); fma2(aR[2], do2, br2.y);
            fma2(aZ[2], de2, bz2.x); fma2(aZ[2], do2, bz2.y);
            fma2(aN[2], de2, bn2.x); fma2(aN[2], do2, bn2.y);
        }
    }
}

extern "C" __global__ void __launch_bounds__(THREADS, 1)
gwm_kernel(const float* __restrict__ x_seq, const float* __restrict__ adj_seq,
           const float* __restrict__ W_gcn, const float* __restrict__ b_gcn,
           const float* __restrict__ W_ih,  const float* __restrict__ W_hh,
           const float* __restrict__ b_ih,  const float* __restrict__ b_hh,
           const float* __restrict__ W_d1,  const float* __restrict__ b_d1,
           const float* __restrict__ W_d2,  const float* __restrict__ b_d2,
           float* __restrict__ out)
{
    extern __shared__ float sm[];
    float* sWp  = sm;                 // packed gate weights (see above)
    float* sC   = sWp  + SZ_WP;       // [48][132] : cols 0..63 spa, 64..127 h
    float* sSup = sC   + MPAD*CS;     // [48][68]
    float* sAdj = sSup + MPAD*SS;     // [r][24]
    float* sX   = sAdj + ROWS*24;
    float* sWg  = sX   + ROWS*FF;     // [j][4]
    float* sbg  = sWg  + 256;
    float* sbrz = sbg  + 64;          // b_ih+b_hh for j 0..127 (r,z)
    float* sbin = sbrz + 128;         // b_ih[128+j]
    float* sbhn = sbin + 64;          // b_hh[128+j]
    float* sWd1 = sbhn + 64;          // [q][64]
    float* sbd1 = sWd1 + 2048;
    float* sWd2 = sbd1 + 32;          // [f][32]
    float* sbd2 = sWd2 + 128;

    const int tid  = threadIdx.x;
    const int w    = tid >> 5;
    const int lane = tid & 31;
    const int b0   = blockIdx.x * BPC;

    // GEMM tile mapping: 16 warps = 2 m-groups (24 rows) x 8 j-groups
    const int wm = w >> 3;            // 0..1
    const int wn = w & 7;             // 0..7
    const int ml = lane & 7;          // 0..7
    const int ng = lane >> 3;         // 0..3
    const int p  = wn*4 + ng;         // j-pair 0..31
    const int p4 = p*4;
    const int jr = p*2;               // even j 0..62
    int rofs[3];
#pragma unroll
    for (int q = 0; q < 3; ++q) rofs[q] = (wm*24 + ml*3 + q)*CS;

    // ---- one-time setup ----
    for (int e = tid; e < SZ_WP; e += THREADS) {
        int k2   = e / 384;
        int rem  = e - k2*384;
        int g    = rem >> 7;          // 0..2
        int rem2 = rem & 127;
        int pp   = rem2 >> 2;         // 0..31
        int qq   = rem2 & 3;
        int j = 2*pp + (qq & 1);
        int k = 2*k2 + (qq >> 1);
        float v = (k < 64) ? W_ih[(g*64 + j)*64 + k]
                           : W_hh[(g*64 + j)*64 + (k - 64)];
        sWp[e] = v;
    }
    for (int e = tid; e < 256;  e += THREADS) sWg[e]  = W_gcn[e];
    for (int e = tid; e < 2048; e += THREADS) sWd1[e] = W_d1[e];
    if (tid < 64)  sbg[tid]  = b_gcn[tid];
    if (tid < 128) sbrz[tid] = b_ih[tid] + b_hh[tid];
    if (tid >= 128 && tid < 192) sbin[tid-128] = b_ih[tid];
    if (tid >= 192 && tid < 256) sbhn[tid-192] = b_hh[tid-64];   // b_hh[128..191]
    if (tid < 32)  sbd1[tid] = b_d1[tid];
    if (tid < 128) sWd2[tid] = W_d2[tid];
    if (tid < 4)   sbd2[tid] = b_d2[tid];
    for (int e = tid; e < MPAD*CS; e += THREADS) sC[e] = 0.f;   // spa=0, h0=0
    __syncthreads();

    for (int t = 0; t < TT + FUT; ++t) {
        const bool hist = (t < TT);
        if (hist) {
            for (int e = tid; e < ROWS*NNODES; e += THREADS) {
                int bl = e / (NNODES*NNODES);
                int i  = e - bl*(NNODES*NNODES);
                int n  = i / NNODES, m = i - n*NNODES;
                sAdj[(bl*NNODES + n)*24 + m] =
                    adj_seq[((size_t)(b0+bl)*TT + t)*(NNODES*NNODES) + i];
            }
            for (int e = tid; e < ROWS*FF; e += THREADS) {
                int bl = e / (NNODES*FF);
                int i  = e - bl*(NNODES*FF);
                sX[e] = x_seq[((size_t)(b0+bl)*TT + t)*(NNODES*FF) + i];
            }
            __syncthreads();
        }

        // ---- phase 1: support = x @ Wg^T + bg ----
        for (int e = tid; e < ROWS*HH; e += THREADS) {
            int r = e >> 6, j = e & 63;
            const float* xp = sX + r*FF;
            float v = sbg[j];
            v = fmaf(xp[0], sWg[j*4+0], v);
            v = fmaf(xp[1], sWg[j*4+1], v);
            v = fmaf(xp[2], sWg[j*4+2], v);
            v = fmaf(xp[3], sWg[j*4+3], v);
            sSup[r*SS + j] = v;
        }
        __syncthreads();

        // ---- phase 2: spa = relu(adj @ support) -> sC[:, 0..63] ----
        {
            const int rh = lane >> 4, jq = lane & 15;
            for (int pp = w; pp < 23; pp += 16) {
                int r  = 2*pp + rh;                   // 0..45
                int bl = r / NNODES;
                const float* arow = sAdj + r*24;
                const float* supb = sSup + (bl*NNODES)*SS;
                u64 a0 = 0ull, a1 = 0ull;
#pragma unroll
                for (int m = 0; m < NNODES; ++m) {
                    u64 am = dup2(arow[m]);
                    ulonglong2 s = *(const ulonglong2*)(supb + m*SS + 4*jq);
                    fma2(a0, am, s.x);
                    fma2(a1, am, s.y);
                }
                float2 f0 = unpk(a0), f1 = unpk(a1);
                float4 o;
                o.x = fmaxf(f0.x, 0.f); o.y = fmaxf(f0.y, 0.f);
                o.z = fmaxf(f1.x, 0.f); o.w = fmaxf(f1.y, 0.f);
                *(float4*)(sC + r*CS + 4*jq) = o;
            }
        }
        __syncthreads();

        // ---- phase 3: gate GEMM ----
        u64 aR[3], aZ[3], aNlo[3], aNhi[3];
#pragma unroll
        for (int q = 0; q < 3; ++q) { aR[q]=0ull; aZ[q]=0ull; aNlo[q]=0ull; aNhi[q]=0ull; }

        gemm_half(sC, sWp, rofs, p4, 0,  aR, aZ, aNlo);  // spa @ W_ih^T
        gemm_half(sC, sWp, rofs, p4, 16, aR, aZ, aNhi);  // h   @ W_hh^T

        // ---- GRU epilogue (in registers) ----
        float hnew[3][2];
        {
            const float2 brz_r = *(const float2*)(sbrz + jr);
            const float2 brz_z = *(const float2*)(sbrz + 64 + jr);
            const float2 bin_n = *(const float2*)(sbin + jr);
            const float2 bhn_n = *(const float2*)(sbhn + jr);
#pragma unroll
            for (int q = 0; q < 3; ++q) {
                float2 rv = unpk(aR[q]);
                float2 zv = unpk(aZ[q]);
                float2 nI = unpk(aNlo[q]);
                float2 nH = unpk(aNhi[q]);
                float r0 = sigmoidf_(rv.x + brz_r.x);
                float r1 = sigmoidf_(rv.y + brz_r.y);
                float z0 = sigmoidf_(zv.x + brz_z.x);
                float z1 = sigmoidf_(zv.y + brz_z.y);
                float n0 = tanhf_(nI.x + bin_n.x + r0*(nH.x + bhn_n.x));
                float n1 = tanhf_(nI.y + bin_n.y + r1*(nH.y + bhn_n.y));
                float2 ho = *(const float2*)(sC + rofs[q] + 64 + jr);
                hnew[q][0] = (1.f - z0)*n0 + z0*ho.x;
                hnew[q][1] = (1.f - z1)*n1 + z1*ho.y;
            }
        }
        __syncthreads();    // all GEMM reads of sC done
#pragma unroll
        for (int q = 0; q < 3; ++q)
            *(float2*)(sC + rofs[q] + 64 + jr) = make_float2(hnew[q][0], hnew[q][1]);
        __syncthreads();

        // ---- decode (future steps only) ----
        if (!hist) {
            const int s = t - TT;
            if (w < 8) {
                const int q0 = w * 4;
#pragma unroll
                for (int rg = 0; rg < 2; ++rg) {
                    int r  = rg*32 + lane;
                    int rr = (r < ROWS) ? r : 0;
                    const float* hp = sC + rr*CS + 64;
                    float acc[4] = {0.f,0.f,0.f,0.f};
#pragma unroll 4
                    for (int kq = 0; kq < 16; ++kq) {
                        float4 hh = *(const float4*)(hp + kq*4);
#pragma unroll
                        for (int jj = 0; jj < 4; ++jj) {
                            const float4 wd = *(const float4*)(sWd1 + (q0+jj)*64 + kq*4);
                            float a = acc[jj];
                            a = fmaf(hh.x, wd.x, a); a = fmaf(hh.y, wd.y, a);
                            a = fmaf(hh.z, wd.z, a); a = fmaf(hh.w, wd.w, a);
                            acc[jj] = a;
                        }
                    }
                    if (r < ROWS) {
#pragma unroll
                        for (int jj = 0; jj < 4; ++jj)
                            sSup[r*SS + q0 + jj] = fmaxf(acc[jj] + sbd1[q0+jj], 0.f);
                    }
                }
            }
            __syncthreads();
            for (int e = tid; e < ROWS*FF; e += THREADS) {
                int r = e >> 2, f = e & 3;
                float v = sbd2[f];
#pragma unroll
                for (int q = 0; q < 32; ++q)
                    v = fmaf(sSup[r*SS + q], sWd2[f*32 + q], v);
                sX[e] = v;
                int bl = r / NNODES, n = r - bl*NNODES;
                out[(((size_t)(b0+bl)*FUT + s)*NNODES + n)*FF + f] = v;
            }
            __syncthreads();
        }
    }
}

extern "C" void kernel_launch(void* const* d_in, const int* in_sizes, int n_in,
                              void* d_out, int out_size) {
    const float* x_seq  = (const float*)d_in[0];
    const float* adj    = (const float*)d_in[1];
    const float* W_gcn  = (const float*)d_in[2];
    const float* b_gcn  = (const float*)d_in[3];
    const float* W_ih   = (const float*)d_in[4];
    const float* W_hh   = (const float*)d_in[5];
    const float* b_ih   = (const float*)d_in[6];
    const float* b_hh   = (const float*)d_in[7];
    const float* W_d1   = (const float*)d_in[8];
    const float* b_d1   = (const float*)d_in[9];
    const float* W_d2   = (const float*)d_in[10];
    const float* b_d2   = (const float*)d_in[11];
    float* out = (float*)d_out;

    const int smem_bytes = SMEM_FLOATS * (int)sizeof(float);
    cudaFuncSetAttribute(gwm_kernel, cudaFuncAttributeMaxDynamicSharedMemorySize, smem_bytes);
    gwm_kernel<<<BATCH / BPC, THREADS, smem_bytes>>>(
        x_seq, adj, W_gcn, b_gcn, W_ih, W_hh, b_ih, b_hh,
        W_d1, b_d1, W_d2, b_d2, out);
}